// round 7
// baseline (speedup 1.0000x reference)
#include <cuda_runtime.h>
#include <cstdint>

// WeightedEmbeddingBag: B=4096, N=200, M=26, VOCAB=100000, D=128
//   d_in[0] input   int32 [B,N]   d_in[1] weights fp32 [B,N]
//   d_in[2] offsets int32 [B,M]   d_in[3] emb     fp32 [VOCAB,D]
// Output fp32 [B,M,D].
//
// Running-accumulator walk with snapshots at offset boundaries (identical
// numerics to the reference cumsum-difference).
//
// R7: two warps per batch row, each owning one 64-float half of D (float2
// per lane). Doubles warp-level parallelism (8192 warps) to close the
// latency gap seen at occ=40%; ids/weights staged once per batch in SMEM
// and shared by the two D-half warps.

#define BB 4096
#define NN 200
#define MM 26
#define BATCHES_PER_CTA 4
#define WARPS_PER_CTA   (BATCHES_PER_CTA * 2)   // 8
#define THREADS         (WARPS_PER_CTA * 32)    // 256
#define UNROLL 8

__global__ __launch_bounds__(THREADS)
void ebag_kernel(const int*    __restrict__ input,
                 const float*  __restrict__ psw,
                 const int*    __restrict__ offsets,
                 const float2* __restrict__ emb2,   // [VOCAB, 64] float2
                 float2*       __restrict__ out2)   // [B, M, 64] float2
{
    __shared__ int   s_id [BATCHES_PER_CTA][NN];
    __shared__ float s_w  [BATCHES_PER_CTA][NN];
    __shared__ int   s_off[BATCHES_PER_CTA][32];

    const int tid = threadIdx.x;
    const int b0  = blockIdx.x * BATCHES_PER_CTA;

    // CTA-wide coalesced preload of 4 batch rows of ids + weights + offsets.
    for (int i = tid; i < BATCHES_PER_CTA * NN; i += THREADS) {
        const int bl = i / NN, n = i - bl * NN;
        s_id[bl][n] = input[(size_t)(b0 + bl) * NN + n];
        s_w [bl][n] = psw  [(size_t)(b0 + bl) * NN + n];
    }
    for (int i = tid; i < BATCHES_PER_CTA * MM; i += THREADS) {
        const int bl = i / MM, m = i - bl * MM;
        s_off[bl][m] = offsets[(size_t)(b0 + bl) * MM + m];
    }
    __syncthreads();

    const int wid  = tid >> 5;
    const int lane = tid & 31;
    const int bl   = wid >> 1;          // local batch 0..3
    const int half = wid & 1;           // D-half 0..1
    const int b    = b0 + bl;
    const int dcol = half * 32 + lane;  // float2 column 0..63

    int nmax = s_off[bl][MM - 1];
    if (nmax > NN - 1) nmax = NN - 1;   // defensive: fail clean, never fault
    if (nmax < 0)      nmax = 0;

    float2 acc  = make_float2(0.f, 0.f);
    float2 snap = make_float2(0.f, 0.f);
    int m   = 0;
    int cur = s_off[bl][0];

    float2* o_b = out2 + (size_t)b * MM * 64;

    for (int n0 = 0; n0 <= nmax; n0 += UNROLL) {
        // UNROLL independent 256B gathers in flight (tail clamps to nmax;
        // duplicate loads are discarded by the j-loop guard).
        float2 v[UNROLL];
        #pragma unroll
        for (int j = 0; j < UNROLL; j++) {
            int n  = n0 + j;
            int nc = (n <= nmax) ? n : nmax;
            v[j] = emb2[(size_t)s_id[bl][nc] * 64 + dcol];
        }

        #pragma unroll
        for (int j = 0; j < UNROLL; j++) {
            const int n = n0 + j;
            if (n <= nmax) {
                const float w = s_w[bl][n];
                acc.x = fmaf(w, v[j].x, acc.x);
                acc.y = fmaf(w, v[j].y, acc.y);

                // Emit every segment ending at n (duplicate offsets -> empty
                // segments -> exact zeros, matching the reference).
                while (cur == n) {
                    o_b[m * 64 + dcol] = make_float2(acc.x - snap.x,
                                                     acc.y - snap.y);
                    snap = acc;
                    m++;
                    cur = (m < MM) ? s_off[bl][m] : -1;
                }
            }
        }
    }
}

extern "C" void kernel_launch(void* const* d_in, const int* in_sizes, int n_in,
                              void* d_out, int out_size)
{
    const int*    input   = (const int*)   d_in[0];
    const float*  psw     = (const float*) d_in[1];
    const int*    offsets = (const int*)   d_in[2];
    const float2* emb2    = (const float2*)d_in[3];
    float2*       out2    = (float2*)d_out;

    dim3 grid(BB / BATCHES_PER_CTA);
    dim3 block(THREADS);
    ebag_kernel<<<grid, block>>>(input, psw, offsets, emb2, out2);
}

// round 8
// speedup vs baseline: 1.3213x; 1.3213x over previous
#include <cuda_runtime.h>
#include <cstdint>

// WeightedEmbeddingBag: B=4096, N=200, M=26, VOCAB=100000, D=128
//   d_in[0] input   int32 [B,N]   d_in[1] weights fp32 [B,N]
//   d_in[2] offsets int32 [B,M]   d_in[3] emb     fp32 [VOCAB,D]
// Output fp32 [B,M,D].
//
// R8: split the N-walk across two warps per batch (n<100 / n>=100), both
// running concurrently with full 512B LDG.128 gathers (lane owns float4).
// Segments fully inside one half are local cumsum-differences; the single
// crossing segment = warp-lo tail remainder R0 (via SMEM) + warp-hi's first
// local prefix, combined after one __syncthreads.

#define BB 4096
#define NN 200
#define MM 26
#define HALF 100
#define BATCHES_PER_CTA 2
#define THREADS 128                 // 4 warps: 2 batches x {lo,hi}
#define UNROLL 8

__global__ __launch_bounds__(THREADS)
void ebag_kernel(const int*    __restrict__ input,
                 const float*  __restrict__ psw,
                 const int*    __restrict__ offsets,
                 const float4* __restrict__ emb4,   // [VOCAB, 32] float4
                 float4*       __restrict__ out4)   // [B, M, 32] float4
{
    __shared__ int    s_id [BATCHES_PER_CTA][NN];
    __shared__ float  s_w  [BATCHES_PER_CTA][NN];
    __shared__ int    s_off[BATCHES_PER_CTA][MM];
    __shared__ float4 s_R0 [BATCHES_PER_CTA][32];   // warp-lo tail remainder

    const int tid = threadIdx.x;
    const int b0  = blockIdx.x * BATCHES_PER_CTA;

    // Coalesced CTA-wide preload of ids/weights/offsets for both batches.
    for (int i = tid; i < BATCHES_PER_CTA * NN; i += THREADS) {
        const int bl = i / NN, n = i - bl * NN;
        s_id[bl][n] = input[(size_t)(b0 + bl) * NN + n];
        s_w [bl][n] = psw  [(size_t)(b0 + bl) * NN + n];
    }
    if (tid < BATCHES_PER_CTA * MM) {
        const int bl = tid / MM, m = tid - bl * MM;
        s_off[bl][m] = offsets[(size_t)(b0 + bl) * MM + m];
    }
    __syncthreads();

    const int wid  = tid >> 5;
    const int lane = tid & 31;
    const int bl   = wid >> 1;      // local batch 0..1
    const int hi   = wid & 1;       // 0 = n<HALF, 1 = n>=HALF
    const int b    = b0 + bl;

    int nmax = s_off[bl][MM - 1];
    if (nmax > NN - 1) nmax = NN - 1;   // defensive: fail clean, never fault
    if (nmax < 0)      nmax = 0;

    float4* o_b = out4 + (size_t)b * MM * 32;

    float4 acc  = make_float4(0.f, 0.f, 0.f, 0.f);
    float4 snap = make_float4(0.f, 0.f, 0.f, 0.f);
    float4 C    = make_float4(0.f, 0.f, 0.f, 0.f);   // deferred crossing value
    int mc = MM;                                     // first m with off >= HALF
    bool do_cross = false;

    if (hi == 0) {
        // ---- lower half: n = 0 .. min(nmax, HALF-1) ----
        const int e0 = (nmax < HALF - 1) ? nmax : (HALF - 1);
        int m   = 0;
        int cur = s_off[bl][0];

        for (int n0 = 0; n0 <= e0; n0 += UNROLL) {
            float4 v[UNROLL];
            #pragma unroll
            for (int j = 0; j < UNROLL; j++) {
                int n  = n0 + j;
                int nc = (n <= e0) ? n : e0;        // tail clamp (dup loads ok)
                v[j] = emb4[(size_t)s_id[bl][nc] * 32 + lane];
            }
            #pragma unroll
            for (int j = 0; j < UNROLL; j++) {
                const int n = n0 + j;
                if (n <= e0) {
                    const float w = s_w[bl][n];
                    acc.x = fmaf(w, v[j].x, acc.x);
                    acc.y = fmaf(w, v[j].y, acc.y);
                    acc.z = fmaf(w, v[j].z, acc.z);
                    acc.w = fmaf(w, v[j].w, acc.w);
                    while (cur == n) {              // emit segments ending here
                        o_b[m * 32 + lane] = make_float4(
                            acc.x - snap.x, acc.y - snap.y,
                            acc.z - snap.z, acc.w - snap.w);
                        snap = acc;
                        m++;
                        cur = (m < MM) ? s_off[bl][m] : NN;  // NN never matches
                    }
                }
            }
        }
        // Tail remainder: sum over [last boundary, e0] -> crossing-segment head.
        s_R0[bl][lane] = make_float4(acc.x - snap.x, acc.y - snap.y,
                                     acc.z - snap.z, acc.w - snap.w);
    } else if (nmax >= HALF) {
        // ---- upper half: n = HALF .. nmax ----
        mc = 0;
        while (mc < MM && s_off[bl][mc] < HALF) mc++;   // first offset >= HALF
        int m   = mc;
        int cur = (m < MM) ? s_off[bl][m] : NN;

        for (int n0 = HALF; n0 <= nmax; n0 += UNROLL) {
            float4 v[UNROLL];
            #pragma unroll
            for (int j = 0; j < UNROLL; j++) {
                int n  = n0 + j;
                int nc = (n <= nmax) ? n : nmax;
                v[j] = emb4[(size_t)s_id[bl][nc] * 32 + lane];
            }
            #pragma unroll
            for (int j = 0; j < UNROLL; j++) {
                const int n = n0 + j;
                if (n <= nmax) {
                    const float w = s_w[bl][n];
                    acc.x = fmaf(w, v[j].x, acc.x);
                    acc.y = fmaf(w, v[j].y, acc.y);
                    acc.z = fmaf(w, v[j].z, acc.z);
                    acc.w = fmaf(w, v[j].w, acc.w);
                    while (cur == n) {
                        float4 d = make_float4(acc.x - snap.x, acc.y - snap.y,
                                               acc.z - snap.z, acc.w - snap.w);
                        if (m == mc) { C = d; do_cross = true; }  // defer: needs R0
                        else o_b[m * 32 + lane] = d;              // purely local
                        snap = acc;
                        m++;
                        cur = (m < MM) ? s_off[bl][m] : NN;
                    }
                }
            }
        }
    }

    __syncthreads();   // orders s_R0 writes before the crossing-segment fixup

    if (do_cross) {
        const float4 r0 = s_R0[bl][lane];
        o_b[mc * 32 + lane] = make_float4(C.x + r0.x, C.y + r0.y,
                                          C.z + r0.z, C.w + r0.w);
    }
}

extern "C" void kernel_launch(void* const* d_in, const int* in_sizes, int n_in,
                              void* d_out, int out_size)
{
    const int*    input   = (const int*)   d_in[0];
    const float*  psw     = (const float*) d_in[1];
    const int*    offsets = (const int*)   d_in[2];
    const float4* emb4    = (const float4*)d_in[3];
    float4*       out4    = (float4*)d_out;

    dim3 grid(BB / BATCHES_PER_CTA);    // 2048
    dim3 block(THREADS);                // 128
    ebag_kernel<<<grid, block>>>(input, psw, offsets, emb4, out4);
}

// round 10
// speedup vs baseline: 1.5995x; 1.2105x over previous
#include <cuda_runtime.h>
#include <cstdint>

// WeightedEmbeddingBag: B=4096, N=200, M=26, VOCAB=100000, D=128
//   d_in[0] input   int32 [B,N]   d_in[1] weights fp32 [B,N]
//   d_in[2] offsets int32 [B,M]   d_in[3] emb     fp32 [VOCAB,D]
// Output fp32 [B,M,D].
//
// Warp-per-batch running accumulator with snapshots at offset boundaries
// (identical numerics to the reference cumsum-difference). R6 structure —
// at the chip LTS cap (~484MB mandatory L2 bytes ~= 39us) — plus:
//  * __stcs streaming stores: output is never re-read; evict-first keeps the
//    51MB table L2-resident (kills ~35MB of refill traffic seen as excess DRAM)
//  * 32-bit gather addressing (id<<9 byte offset; id < 2^17 so it fits)
//    and hoisted per-lane byte offset -> fewer ALU ops in the hot loop.

#define BB 4096
#define NN 200
#define MM 26
#define WARPS_PER_CTA 4
#define UNROLL 8

__global__ __launch_bounds__(32 * WARPS_PER_CTA)
void ebag_kernel(const int*   __restrict__ input,
                 const float* __restrict__ psw,
                 const int*   __restrict__ offsets,
                 const char*  __restrict__ emb_bytes,  // emb as bytes, row=512B
                 float4*      __restrict__ out4)       // [B, M, 32] float4
{
    const int wid  = threadIdx.x >> 5;
    const int lane = threadIdx.x & 31;
    const int b    = blockIdx.x * WARPS_PER_CTA + wid;
    if (b >= BB) return;

    __shared__ int   s_id[WARPS_PER_CTA][NN];
    __shared__ float s_w [WARPS_PER_CTA][NN];
    __shared__ int   s_off[WARPS_PER_CTA][32];

    const int*   in_b = input + (size_t)b * NN;
    const float* w_b  = psw   + (size_t)b * NN;

    // Coalesced one-time preload of this batch row's ids + weights.
    #pragma unroll
    for (int n = lane; n < NN; n += 32) {
        s_id[wid][n] = in_b[n];
        s_w [wid][n] = w_b[n];
    }
    if (lane < MM)
        s_off[wid][lane] = offsets[(size_t)b * MM + lane];
    __syncwarp();

    // Per-lane base: lane's 16B slice within each 512B embedding row.
    const char* emb_lane = emb_bytes + (unsigned)(lane << 4);
    float4*     o_b      = out4 + (size_t)b * MM * 32;

    int nmax = s_off[wid][MM - 1];
    if (nmax > NN - 1) nmax = NN - 1;   // defensive: fail clean, never fault
    if (nmax < 0)      nmax = 0;

    float4 acc  = make_float4(0.f, 0.f, 0.f, 0.f);
    float4 snap = make_float4(0.f, 0.f, 0.f, 0.f);
    int m   = 0;
    int cur = s_off[wid][0];

    for (int n0 = 0; n0 <= nmax; n0 += UNROLL) {
        // UNROLL independent 512B gathers in flight (tail clamps to nmax;
        // duplicate loads are discarded by the j-loop guard). 32-bit offset:
        // id < 100000 -> id<<9 < 2^26.
        float4 v[UNROLL];
        #pragma unroll
        for (int j = 0; j < UNROLL; j++) {
            int n  = n0 + j;
            int nc = (n <= nmax) ? n : nmax;
            const unsigned off = (unsigned)s_id[wid][nc] << 9;
            v[j] = *(const float4*)(emb_lane + off);
        }

        #pragma unroll
        for (int j = 0; j < UNROLL; j++) {
            const int n = n0 + j;
            if (n <= nmax) {
                const float w = s_w[wid][n];
                acc.x = fmaf(w, v[j].x, acc.x);
                acc.y = fmaf(w, v[j].y, acc.y);
                acc.z = fmaf(w, v[j].z, acc.z);
                acc.w = fmaf(w, v[j].w, acc.w);

                // Emit every segment ending at n (duplicate offsets -> empty
                // segments -> exact zeros, matching the reference).
                while (cur == n) {
                    float4 r = make_float4(acc.x - snap.x, acc.y - snap.y,
                                           acc.z - snap.z, acc.w - snap.w);
                    __stcs(&o_b[m * 32 + lane], r);   // streaming: don't evict table
                    snap = acc;
                    m++;
                    cur = (m < MM) ? s_off[wid][m] : NN;  // NN never matches
                }
            }
        }
    }
}

extern "C" void kernel_launch(void* const* d_in, const int* in_sizes, int n_in,
                              void* d_out, int out_size)
{
    const int*   input   = (const int*)  d_in[0];
    const float* psw     = (const float*)d_in[1];
    const int*   offsets = (const int*)  d_in[2];
    const char*  emb     = (const char*) d_in[3];
    float4*      out4    = (float4*)d_out;

    dim3 grid(BB / WARPS_PER_CTA);
    dim3 block(32 * WARPS_PER_CTA);
    ebag_kernel<<<grid, block>>>(input, psw, offsets, emb, out4);
}